// round 1
// baseline (speedup 1.0000x reference)
#include <cuda_runtime.h>
#include <cuda_bf16.h>

#define N_LEVELS 64

// Each thread processes 4 elements via float4.
// out_vals[i]   = levels[best_idx(i)]           (the ST-estimator value == quantized value)
// out_idx[i]    = (float)best_idx(i)            (only written when write_idx != 0)
__global__ void __launch_bounds__(256) quantizer_kernel(
    const float* __restrict__ x,
    const float* __restrict__ levels,
    float* __restrict__ out_vals,
    float* __restrict__ out_idx,
    int n, int write_idx)
{
    __shared__ float lv[N_LEVELS];
    if (threadIdx.x < N_LEVELS) lv[threadIdx.x] = levels[threadIdx.x];
    __syncthreads();

    int base = (blockIdx.x * blockDim.x + threadIdx.x) * 4;
    if (base >= n) return;

    float4 xv = *reinterpret_cast<const float4*>(x + base);

    float vin[4] = {xv.x, xv.y, xv.z, xv.w};
    float qv[4];
    float qi[4];

    #pragma unroll
    for (int k = 0; k < 4; k++) {
        float t = tanhf(vin[k]);
        // levels = linspace(-1, 1, 64): step = 2/63, so analytic nearest index:
        float f = (t + 1.0f) * 31.5f;
        int c = (int)floorf(f + 0.5f);
        c = max(0, min(N_LEVELS - 1, c));

        // Exact fixup against the real level values (handles linspace rounding
        // and ties; argmin takes the FIRST minimum -> tie goes to lower index).
        int best = c;
        float dbest = fabsf(lv[best] - t);
        if (c > 0) {
            float dl = fabsf(lv[c - 1] - t);
            if (dl <= dbest) { best = c - 1; dbest = dl; }
        }
        if (c < N_LEVELS - 1) {
            float dh = fabsf(lv[c + 1] - t);
            if (dh < dbest) { best = c + 1; dbest = dh; }
        }

        qv[k] = lv[best];
        qi[k] = (float)best;
    }

    float4 ov = make_float4(qv[0], qv[1], qv[2], qv[3]);
    *reinterpret_cast<float4*>(out_vals + base) = ov;

    if (write_idx) {
        float4 oi = make_float4(qi[0], qi[1], qi[2], qi[3]);
        *reinterpret_cast<float4*>(out_idx + base) = oi;
    }
}

extern "C" void kernel_launch(void* const* d_in, const int* in_sizes, int n_in,
                              void* d_out, int out_size) {
    const float* x      = (const float*)d_in[0];
    const float* levels = (const float*)d_in[1];
    float* out          = (float*)d_out;

    int n = in_sizes[0];            // 4194304 elements of x
    int write_idx = (out_size >= 2 * n) ? 1 : 0;
    float* out_idx = out + n;       // second plane (index output), if present

    int threads = 256;
    int elems_per_block = threads * 4;
    int blocks = (n + elems_per_block - 1) / elems_per_block;

    quantizer_kernel<<<blocks, threads>>>(x, levels, out, out_idx, n, write_idx);
}